// round 10
// baseline (speedup 1.0000x reference)
#include <cuda_runtime.h>
#include <math.h>
#include <cstdint>

#define N_NODES 200000
#define N_EDGES 1250000
#define N_GRAPHS 2048
#define IN_CH 128
#define HID 64
#define EMB 32

// ---------------- scratch (static device globals; no allocation) ----------------
__device__ int   g_is64;
__device__ int   g_deg[N_NODES];
__device__ float g_dis[N_NODES];
__device__ int   g_off[N_NODES];
__device__ int   g_cur[N_NODES];
__device__ int   g_csr[N_EDGES];
__device__ int   g_bsums[256];
__device__ __align__(16) float g_h1[(size_t)N_NODES * 64];   // GEMM output
__device__ __align__(16) float g_h2[(size_t)N_NODES * 64];   // AGG output / GEMM input

__device__ __forceinline__ long long load_idx(const void* p, long long i, int is64) {
    if (is64) return ((const long long*)p)[i];
    return (long long)((const int*)p)[i];
}

// ---------------- zero degree + dtype detect (fused) ----------------
__global__ void k_zero_detect(const unsigned* __restrict__ ei_words) {
    int i = blockIdx.x * 1024 + threadIdx.x;
    if (i < N_NODES) g_deg[i] = 0;
    if (blockIdx.x == 0 && threadIdx.x < 128) {
        unsigned w = ei_words[2 * threadIdx.x + 1];
        unsigned any = __ballot_sync(0xffffffffu, w != 0u);
        __shared__ unsigned s_any[4];
        if ((threadIdx.x & 31) == 0) s_any[threadIdx.x >> 5] = any;
        __syncthreads();
        if (threadIdx.x == 0) {
            unsigned t = s_any[0] | s_any[1] | s_any[2] | s_any[3];
            g_is64 = t ? 0 : 1;
        }
    }
}

// ---------------- block inclusive scan ----------------
template <int NT>
__device__ __forceinline__ int block_inclusive_scan(int v, int tid) {
    int lane = tid & 31, w = tid >> 5;
    int x = v;
#pragma unroll
    for (int o = 1; o < 32; o <<= 1) {
        int y = __shfl_up_sync(0xffffffffu, x, o);
        if (lane >= o) x += y;
    }
    __shared__ int wsum[NT / 32];
    if (lane == 31) wsum[w] = x;
    __syncthreads();
    if (w == 0) {
        const int NW = NT / 32;
        int s = (lane < NW) ? wsum[lane] : 0;
#pragma unroll
        for (int o = 1; o < 32; o <<= 1) {
            int y = __shfl_up_sync(0xffffffffu, s, o);
            if (lane >= o) s += y;
        }
        if (lane < NW) wsum[lane] = s;
    }
    __syncthreads();
    return x + (w ? wsum[w - 1] : 0);
}

// ---------------- graph preprocessing ----------------
__global__ void k_count_deg(const void* __restrict__ ei) {
    int e = blockIdx.x * 256 + threadIdx.x;
    int is64 = g_is64;
    if (e < N_EDGES) {
        int d = (int)load_idx(ei, (long long)N_EDGES + e, is64);
        if (d >= 0 && d < N_NODES) atomicAdd(&g_deg[d], 1);
    }
}

__global__ void k_scan1() {
    int idx = blockIdx.x * 1024 + threadIdx.x;
    int v = (idx < N_NODES) ? g_deg[idx] : 0;
    int incl = block_inclusive_scan<1024>(v, threadIdx.x);
    if (idx < N_NODES) g_off[idx] = incl - v;
    if (threadIdx.x == 1023) g_bsums[blockIdx.x] = incl;
}

__global__ void k_scan2(int nb) {
    int v = ((int)threadIdx.x < nb) ? g_bsums[threadIdx.x] : 0;
    int incl = block_inclusive_scan<256>(v, threadIdx.x);
    if ((int)threadIdx.x < nb) g_bsums[threadIdx.x] = incl - v;
}

__global__ void k_scan3() {
    int idx = blockIdx.x * 256 + threadIdx.x;
    if (idx < N_NODES) {
        int o = g_off[idx] + g_bsums[idx >> 10];
        g_off[idx] = o;
        g_cur[idx] = o;
        g_dis[idx] = rsqrtf(1.0f + (float)g_deg[idx]);
    }
}

__global__ void k_fill_csr(const void* __restrict__ ei) {
    int e = blockIdx.x * 256 + threadIdx.x;
    int is64 = g_is64;
    if (e < N_EDGES) {
        int s = (int)load_idx(ei, e, is64);
        int d = (int)load_idx(ei, (long long)N_EDGES + e, is64);
        if (d >= 0 && d < N_NODES && s >= 0 && s < N_NODES) {
            int p = atomicAdd(&g_cur[d], 1);
            g_csr[p] = s;
        }
    }
}

// ---------------- tiled fp32 GEMM with packed f32x2 FMA (R9 proven) ----------------
template <int K, int NO, bool EXT>
__global__ void __launch_bounds__(256) k_gemm(const float* __restrict__ Xext,
                                              const float* __restrict__ W, int nrows) {
    constexpr int BM = 128, BK = 64;
    constexpr int TN = NO / 16;  // 4 for NO=64, 2 for NO=32
    constexpr int NKC = K / BK;
    __shared__ float xs[BK][BM];
    __shared__ float ws[BK][NO];

    const float* X = EXT ? Xext : (const float*)g_h2;
    float* Y = (float*)g_h1;

    const int tid = threadIdx.x;
    const int tr = tid >> 4;
    const int tc = tid & 15;
    const int row0 = blockIdx.x * BM;

    const int lr = tid & 127;
    const int lhalf = tid >> 7;
    const int gr_load = row0 + lr;
    const bool ld_ok = (gr_load < nrows);
    const float4* Xr = (const float4*)(X + (size_t)gr_load * K);

    uint64_t acc2[4][TN];
#pragma unroll
    for (int p = 0; p < 4; p++)
#pragma unroll
        for (int j = 0; j < TN; j++) acc2[p][j] = 0ull;

#pragma unroll
    for (int kc = 0; kc < NKC; kc++) {
        if (kc > 0) __syncthreads();
#pragma unroll
        for (int t = 0; t < 8; t++) {
            int c4 = lhalf * 8 + t;
            float4 v = ld_ok ? Xr[kc * (BK / 4) + c4] : make_float4(0.f, 0.f, 0.f, 0.f);
            int k0 = c4 * 4;
            xs[k0 + 0][lr] = v.x; xs[k0 + 1][lr] = v.y;
            xs[k0 + 2][lr] = v.z; xs[k0 + 3][lr] = v.w;
        }
        {
            const float4* W4 = (const float4*)(W + (size_t)kc * BK * NO);
            float4* ws4 = (float4*)ws;
#pragma unroll
            for (int t = tid; t < BK * NO / 4; t += 256) ws4[t] = W4[t];
        }
        __syncthreads();

#pragma unroll 8
        for (int k = 0; k < BK; k++) {
            ulonglong2 xlo = *(const ulonglong2*)&xs[k][tr * 8];
            ulonglong2 xhi = *(const ulonglong2*)&xs[k][tr * 8 + 4];
            uint64_t xp[4] = {xlo.x, xlo.y, xhi.x, xhi.y};
            float wv[TN];
            if (TN == 4) {
                *(float4*)&wv[0] = *(const float4*)&ws[k][tc * 4];
            } else {
                *(float2*)&wv[0] = *(const float2*)&ws[k][tc * 2];
            }
            uint64_t wp[TN];
#pragma unroll
            for (int j = 0; j < TN; j++) {
                unsigned wb = __float_as_uint(wv[j]);
                asm("mov.b64 %0, {%1, %1};" : "=l"(wp[j]) : "r"(wb));
            }
#pragma unroll
            for (int p = 0; p < 4; p++)
#pragma unroll
                for (int j = 0; j < TN; j++)
                    asm("fma.rn.f32x2 %0, %1, %2, %0;"
                        : "+l"(acc2[p][j]) : "l"(xp[p]), "l"(wp[j]));
        }
    }

    float acc[8][TN];
#pragma unroll
    for (int p = 0; p < 4; p++)
#pragma unroll
        for (int j = 0; j < TN; j++) {
            unsigned lo, hi;
            asm("mov.b64 {%0, %1}, %2;" : "=r"(lo), "=r"(hi) : "l"(acc2[p][j]));
            acc[2 * p][j] = __uint_as_float(lo);
            acc[2 * p + 1][j] = __uint_as_float(hi);
        }

#pragma unroll
    for (int i = 0; i < 8; i++) {
        int r = row0 + tr * 8 + i;
        if (r < nrows) {
            if (TN == 4) {
                float4 o = make_float4(acc[i][0], acc[i][1], acc[i][2], acc[i][3]);
                *reinterpret_cast<float4*>(&Y[(size_t)r * NO + tc * 4]) = o;
            } else {
                float2 o = make_float2(acc[i][0], acc[i][1]);
                *reinterpret_cast<float2*>(&Y[(size_t)r * NO + tc * 2]) = o;
            }
        }
    }
}

// ---------------- aggregation: 4-edge unrolled gather ----------------
__global__ void k_agg64(const float* __restrict__ b) {
    int warp = (blockIdx.x * blockDim.x + threadIdx.x) >> 5;
    int lane = threadIdx.x & 31;
    if (warp >= N_NODES) return;
    const float* hin = (const float*)g_h1;
    float* hout = (float*)g_h2;

    int i = warp;
    float di = g_dis[i];
    int start = g_off[i];
    int cnt = g_deg[i];

    float ax = 0.f, ay = 0.f, bx = 0.f, by = 0.f;
    float cx = 0.f, cy = 0.f, dx = 0.f, dy = 0.f;
    int j = 0;
    for (; j + 4 <= cnt; j += 4) {
        int s0 = __ldg(&g_csr[start + j]);
        int s1 = __ldg(&g_csr[start + j + 1]);
        int s2 = __ldg(&g_csr[start + j + 2]);
        int s3 = __ldg(&g_csr[start + j + 3]);
        float f0 = __ldg(&g_dis[s0]);
        float f1 = __ldg(&g_dis[s1]);
        float f2 = __ldg(&g_dis[s2]);
        float f3 = __ldg(&g_dis[s3]);
        float2 v0 = *(const float2*)(hin + (size_t)s0 * 64 + 2 * lane);
        float2 v1 = *(const float2*)(hin + (size_t)s1 * 64 + 2 * lane);
        float2 v2 = *(const float2*)(hin + (size_t)s2 * 64 + 2 * lane);
        float2 v3 = *(const float2*)(hin + (size_t)s3 * 64 + 2 * lane);
        ax = fmaf(f0, v0.x, ax); ay = fmaf(f0, v0.y, ay);
        bx = fmaf(f1, v1.x, bx); by = fmaf(f1, v1.y, by);
        cx = fmaf(f2, v2.x, cx); cy = fmaf(f2, v2.y, cy);
        dx = fmaf(f3, v3.x, dx); dy = fmaf(f3, v3.y, dy);
    }
    for (; j < cnt; j++) {
        int s0 = __ldg(&g_csr[start + j]);
        float f0 = __ldg(&g_dis[s0]);
        float2 v0 = *(const float2*)(hin + (size_t)s0 * 64 + 2 * lane);
        ax = fmaf(f0, v0.x, ax); ay = fmaf(f0, v0.y, ay);
    }
    ax += bx + cx + dx;
    ay += by + cy + dy;

    float2 hi = *(const float2*)(hin + (size_t)i * 64 + 2 * lane);
    float2 bb = *(const float2*)(b + 2 * lane);
    float dii = di * di;
    float ox = fmaf(di, ax, fmaf(dii, hi.x, bb.x));
    float oy = fmaf(di, ay, fmaf(dii, hi.y, bb.y));
    *(float2*)(hout + (size_t)i * 64 + 2 * lane) = make_float2(fmaxf(ox, 0.f), fmaxf(oy, 0.f));
}

__global__ void k_agg32(const float* __restrict__ b) {
    int warp = (blockIdx.x * blockDim.x + threadIdx.x) >> 5;
    int lane = threadIdx.x & 31;
    if (warp >= N_NODES) return;
    const float* hin = (const float*)g_h1;
    float* hout = (float*)g_h2;

    int i = warp;
    float di = g_dis[i];
    int start = g_off[i];
    int cnt = g_deg[i];

    float a0 = 0.f, b0 = 0.f, c0 = 0.f, d0 = 0.f;
    int j = 0;
    for (; j + 4 <= cnt; j += 4) {
        int s0 = __ldg(&g_csr[start + j]);
        int s1 = __ldg(&g_csr[start + j + 1]);
        int s2 = __ldg(&g_csr[start + j + 2]);
        int s3 = __ldg(&g_csr[start + j + 3]);
        float f0 = __ldg(&g_dis[s0]);
        float f1 = __ldg(&g_dis[s1]);
        float f2 = __ldg(&g_dis[s2]);
        float f3 = __ldg(&g_dis[s3]);
        a0 = fmaf(f0, hin[(size_t)s0 * 32 + lane], a0);
        b0 = fmaf(f1, hin[(size_t)s1 * 32 + lane], b0);
        c0 = fmaf(f2, hin[(size_t)s2 * 32 + lane], c0);
        d0 = fmaf(f3, hin[(size_t)s3 * 32 + lane], d0);
    }
    for (; j < cnt; j++) {
        int s0 = __ldg(&g_csr[start + j]);
        float f0 = __ldg(&g_dis[s0]);
        a0 = fmaf(f0, hin[(size_t)s0 * 32 + lane], a0);
    }
    a0 += b0 + c0 + d0;

    float o0 = fmaf(di, a0, fmaf(di * di, hin[(size_t)i * 32 + lane], b[lane]));
    hout[(size_t)i * 32 + lane] = fmaxf(o0, 0.0f);
}

// ---------------- pool + classifier (batch sorted) ----------------
__device__ __forceinline__ int lowerb(const void* a, int n, long long key, int is64) {
    int lo = 0, hi = n;
    while (lo < hi) {
        int mid = (lo + hi) >> 1;
        if (load_idx(a, mid, is64) < key) lo = mid + 1; else hi = mid;
    }
    return lo;
}

__global__ void k_pool(const void* __restrict__ batch,
                       const float* __restrict__ Wc1, const float* __restrict__ bc1,
                       const float* __restrict__ Wc2, const float* __restrict__ bc2,
                       float* __restrict__ out) {
    int warp = (blockIdx.x * blockDim.x + threadIdx.x) >> 5;
    int lane = threadIdx.x & 31;
    int wl = (threadIdx.x >> 5);
    if (warp >= N_GRAPHS) return;
    const float* h3 = (const float*)g_h2;
    int is64 = g_is64;

    long long g = warp;
    int start = lowerb(batch, N_NODES, g, is64);
    int end = lowerb(batch, N_NODES, g + 1, is64);

    float acc = 0.0f;
    for (int r = start; r < end; r++) acc += h3[(size_t)r * EMB + lane];
    float cnt = (float)(end - start);
    float emb = acc / fmaxf(cnt, 1.0f);

    __shared__ float sh[8][EMB];
    sh[wl][lane] = emb;
    __syncwarp();

    float partial = 0.0f;
    if (lane < 16) {
        float t = bc1[lane];
#pragma unroll
        for (int c = 0; c < EMB; c++) t = fmaf(sh[wl][c], Wc1[c * 16 + lane], t);
        t = fmaxf(t, 0.0f);
        partial = t * Wc2[lane];
    }
#pragma unroll
    for (int o = 8; o > 0; o >>= 1) partial += __shfl_down_sync(0xffffffffu, partial, o);
    if (lane == 0) out[g] = partial + bc2[0];
}

// ---------------- launch ----------------
extern "C" void kernel_launch(void* const* d_in, const int* in_sizes, int n_in,
                              void* d_out, int out_size) {
    const float* x     = (const float*)d_in[0];
    const void*  ei    = d_in[1];
    const void*  batch = d_in[2];
    const float* W1 = (const float*)d_in[3];  const float* b1 = (const float*)d_in[4];
    const float* W2 = (const float*)d_in[5];  const float* b2 = (const float*)d_in[6];
    const float* W3 = (const float*)d_in[7];  const float* b3 = (const float*)d_in[8];
    const float* Wc1 = (const float*)d_in[9]; const float* bc1 = (const float*)d_in[10];
    const float* Wc2 = (const float*)d_in[11]; const float* bc2 = (const float*)d_in[12];
    float* out = (float*)d_out;

    const int NB_N1024 = (N_NODES + 1023) / 1024;   // 196
    const int NB_E256  = (N_EDGES + 255) / 256;     // 4883
    const int NB_N256  = (N_NODES + 255) / 256;

    const int GEMM_BLKS = (N_NODES + 127) / 128;        // 1563
    const int AGG_BLKS  = (N_NODES * 32 + 255) / 256;   // 25000

    // preprocessing (gemm1 interleaved at launch slot #5 for ncu -s 5 -c 1;
    // fill_csr only feeds agg, so moving gemm1 before it is dependency-safe)
    k_zero_detect<<<NB_N1024, 1024>>>((const unsigned*)ei);   // 0
    k_count_deg<<<NB_E256, 256>>>(ei);                        // 1
    k_scan1<<<NB_N1024, 1024>>>();                            // 2
    k_scan2<<<1, 256>>>(NB_N1024);                            // 3
    k_scan3<<<NB_N256, 256>>>();                              // 4
    k_gemm<128, 64, true><<<GEMM_BLKS, 256>>>(x, W1, N_NODES);// 5  <- profiled
    k_fill_csr<<<NB_E256, 256>>>(ei);                         // 6

    // layer 1 aggregation
    k_agg64<<<AGG_BLKS, 256>>>(b1);
    // layer 2: 64 -> 64
    k_gemm<64, 64, false><<<GEMM_BLKS, 256>>>(nullptr, W2, N_NODES);
    k_agg64<<<AGG_BLKS, 256>>>(b2);
    // layer 3: 64 -> 32
    k_gemm<64, 32, false><<<GEMM_BLKS, 256>>>(nullptr, W3, N_NODES);
    k_agg32<<<AGG_BLKS, 256>>>(b3);

    // pool + classifier
    k_pool<<<N_GRAPHS / 8, 256>>>(batch, Wc1, bc1, Wc2, bc2, out);
}

// round 11
// speedup vs baseline: 1.1405x; 1.1405x over previous
#include <cuda_runtime.h>
#include <math.h>
#include <cstdint>

#define N_NODES 200000
#define N_EDGES 1250000
#define N_GRAPHS 2048
#define IN_CH 128
#define HID 64
#define EMB 32

// ---------------- scratch (static device globals; no allocation) ----------------
__device__ int   g_is64;
__device__ int   g_deg[N_NODES];
__device__ float g_dis[N_NODES];
__device__ int   g_off[N_NODES];
__device__ int   g_cur[N_NODES];
__device__ int   g_csr[N_EDGES];
__device__ int   g_bsums[256];
__device__ __align__(16) float g_h1[(size_t)N_NODES * 64];   // GEMM output
__device__ __align__(16) float g_h2[(size_t)N_NODES * 64];   // AGG output / GEMM input

__device__ __forceinline__ long long load_idx(const void* p, long long i, int is64) {
    if (is64) return ((const long long*)p)[i];
    return (long long)((const int*)p)[i];
}

// ---------------- zero degree + dtype detect (fused) ----------------
__global__ void k_zero_detect(const unsigned* __restrict__ ei_words) {
    int i = blockIdx.x * 1024 + threadIdx.x;
    if (i < N_NODES) g_deg[i] = 0;
    if (blockIdx.x == 0 && threadIdx.x < 128) {
        unsigned w = ei_words[2 * threadIdx.x + 1];
        unsigned any = __ballot_sync(0xffffffffu, w != 0u);
        __shared__ unsigned s_any[4];
        if ((threadIdx.x & 31) == 0) s_any[threadIdx.x >> 5] = any;
        __syncthreads();
        if (threadIdx.x == 0) {
            unsigned t = s_any[0] | s_any[1] | s_any[2] | s_any[3];
            g_is64 = t ? 0 : 1;
        }
    }
}

// ---------------- block inclusive scan ----------------
template <int NT>
__device__ __forceinline__ int block_inclusive_scan(int v, int tid) {
    int lane = tid & 31, w = tid >> 5;
    int x = v;
#pragma unroll
    for (int o = 1; o < 32; o <<= 1) {
        int y = __shfl_up_sync(0xffffffffu, x, o);
        if (lane >= o) x += y;
    }
    __shared__ int wsum[NT / 32];
    if (lane == 31) wsum[w] = x;
    __syncthreads();
    if (w == 0) {
        const int NW = NT / 32;
        int s = (lane < NW) ? wsum[lane] : 0;
#pragma unroll
        for (int o = 1; o < 32; o <<= 1) {
            int y = __shfl_up_sync(0xffffffffu, s, o);
            if (lane >= o) s += y;
        }
        if (lane < NW) wsum[lane] = s;
    }
    __syncthreads();
    return x + (w ? wsum[w - 1] : 0);
}

// ---------------- graph preprocessing ----------------
__global__ void k_scan1() {
    int idx = blockIdx.x * 1024 + threadIdx.x;
    int v = (idx < N_NODES) ? g_deg[idx] : 0;
    int incl = block_inclusive_scan<1024>(v, threadIdx.x);
    if (idx < N_NODES) g_off[idx] = incl - v;
    if (threadIdx.x == 1023) g_bsums[blockIdx.x] = incl;
}

__global__ void k_scan2(int nb) {
    int v = ((int)threadIdx.x < nb) ? g_bsums[threadIdx.x] : 0;
    int incl = block_inclusive_scan<256>(v, threadIdx.x);
    if ((int)threadIdx.x < nb) g_bsums[threadIdx.x] = incl - v;
}

__global__ void k_scan3() {
    int idx = blockIdx.x * 256 + threadIdx.x;
    if (idx < N_NODES) {
        int o = g_off[idx] + g_bsums[idx >> 10];
        g_off[idx] = o;
        g_cur[idx] = o;
        g_dis[idx] = rsqrtf(1.0f + (float)g_deg[idx]);
    }
}

__global__ void k_fill_csr(const void* __restrict__ ei) {
    int e = blockIdx.x * 256 + threadIdx.x;
    int is64 = g_is64;
    if (e < N_EDGES) {
        int s = (int)load_idx(ei, e, is64);
        int d = (int)load_idx(ei, (long long)N_EDGES + e, is64);
        if (d >= 0 && d < N_NODES && s >= 0 && s < N_NODES) {
            int p = atomicAdd(&g_cur[d], 1);
            g_csr[p] = s;
        }
    }
}

// ---------------- tiled fp32 GEMM with packed f32x2 FMA (R9 proven) ----------------
// FUSE_COUNT: blocks >= gemm_blks run the degree-count instead (hidden under GEMM).
template <int K, int NO, bool EXT, bool FUSE_COUNT>
__global__ void __launch_bounds__(256) k_gemm(const float* __restrict__ Xext,
                                              const float* __restrict__ W, int nrows,
                                              int gemm_blks, const void* __restrict__ ei) {
    constexpr int BM = 128, BK = 64;
    constexpr int TN = NO / 16;  // 4 for NO=64, 2 for NO=32
    constexpr int NKC = K / BK;

    if (FUSE_COUNT && (int)blockIdx.x >= gemm_blks) {
        // -------- degree count: 4 edges per thread --------
        int cb = blockIdx.x - gemm_blks;
        int is64 = g_is64;
#pragma unroll
        for (int t = 0; t < 4; t++) {
            int e = cb * 1024 + t * 256 + threadIdx.x;
            if (e < N_EDGES) {
                int d = (int)load_idx(ei, (long long)N_EDGES + e, is64);
                if (d >= 0 && d < N_NODES) atomicAdd(&g_deg[d], 1);
            }
        }
        return;
    }

    __shared__ float xs[BK][BM];
    __shared__ float ws[BK][NO];

    const float* X = EXT ? Xext : (const float*)g_h2;
    float* Y = (float*)g_h1;

    const int tid = threadIdx.x;
    const int tr = tid >> 4;
    const int tc = tid & 15;
    const int row0 = blockIdx.x * BM;

    const int lr = tid & 127;
    const int lhalf = tid >> 7;
    const int gr_load = row0 + lr;
    const bool ld_ok = (gr_load < nrows);
    const float4* Xr = (const float4*)(X + (size_t)gr_load * K);

    uint64_t acc2[4][TN];
#pragma unroll
    for (int p = 0; p < 4; p++)
#pragma unroll
        for (int j = 0; j < TN; j++) acc2[p][j] = 0ull;

#pragma unroll
    for (int kc = 0; kc < NKC; kc++) {
        if (kc > 0) __syncthreads();
#pragma unroll
        for (int t = 0; t < 8; t++) {
            int c4 = lhalf * 8 + t;
            float4 v = ld_ok ? Xr[kc * (BK / 4) + c4] : make_float4(0.f, 0.f, 0.f, 0.f);
            int k0 = c4 * 4;
            xs[k0 + 0][lr] = v.x; xs[k0 + 1][lr] = v.y;
            xs[k0 + 2][lr] = v.z; xs[k0 + 3][lr] = v.w;
        }
        {
            const float4* W4 = (const float4*)(W + (size_t)kc * BK * NO);
            float4* ws4 = (float4*)ws;
#pragma unroll
            for (int t = tid; t < BK * NO / 4; t += 256) ws4[t] = W4[t];
        }
        __syncthreads();

#pragma unroll 8
        for (int k = 0; k < BK; k++) {
            ulonglong2 xlo = *(const ulonglong2*)&xs[k][tr * 8];
            ulonglong2 xhi = *(const ulonglong2*)&xs[k][tr * 8 + 4];
            uint64_t xp[4] = {xlo.x, xlo.y, xhi.x, xhi.y};
            float wv[TN];
            if (TN == 4) {
                *(float4*)&wv[0] = *(const float4*)&ws[k][tc * 4];
            } else {
                *(float2*)&wv[0] = *(const float2*)&ws[k][tc * 2];
            }
            uint64_t wp[TN];
#pragma unroll
            for (int j = 0; j < TN; j++) {
                unsigned wb = __float_as_uint(wv[j]);
                asm("mov.b64 %0, {%1, %1};" : "=l"(wp[j]) : "r"(wb));
            }
#pragma unroll
            for (int p = 0; p < 4; p++)
#pragma unroll
                for (int j = 0; j < TN; j++)
                    asm("fma.rn.f32x2 %0, %1, %2, %0;"
                        : "+l"(acc2[p][j]) : "l"(xp[p]), "l"(wp[j]));
        }
    }

    float acc[8][TN];
#pragma unroll
    for (int p = 0; p < 4; p++)
#pragma unroll
        for (int j = 0; j < TN; j++) {
            unsigned lo, hi;
            asm("mov.b64 {%0, %1}, %2;" : "=r"(lo), "=r"(hi) : "l"(acc2[p][j]));
            acc[2 * p][j] = __uint_as_float(lo);
            acc[2 * p + 1][j] = __uint_as_float(hi);
        }

#pragma unroll
    for (int i = 0; i < 8; i++) {
        int r = row0 + tr * 8 + i;
        if (r < nrows) {
            if (TN == 4) {
                float4 o = make_float4(acc[i][0], acc[i][1], acc[i][2], acc[i][3]);
                *reinterpret_cast<float4*>(&Y[(size_t)r * NO + tc * 4]) = o;
            } else {
                float2 o = make_float2(acc[i][0], acc[i][1]);
                *reinterpret_cast<float2*>(&Y[(size_t)r * NO + tc * 2]) = o;
            }
        }
    }
}

// ---------------- aggregation (R8/R9 proven 2-edge unroll) ----------------
__global__ void k_agg64(const float* __restrict__ b) {
    int warp = (blockIdx.x * blockDim.x + threadIdx.x) >> 5;
    int lane = threadIdx.x & 31;
    if (warp >= N_NODES) return;
    const float* hin = (const float*)g_h1;
    float* hout = (float*)g_h2;

    int i = warp;
    float di = g_dis[i];
    int start = g_off[i];
    int cnt = g_deg[i];

    float ax = 0.f, ay = 0.f, bx = 0.f, by = 0.f;
    int j = 0;
    for (; j + 2 <= cnt; j += 2) {
        int s0 = __ldg(&g_csr[start + j]);
        int s1 = __ldg(&g_csr[start + j + 1]);
        float f0 = __ldg(&g_dis[s0]);
        float f1 = __ldg(&g_dis[s1]);
        float2 v0 = *(const float2*)(hin + (size_t)s0 * 64 + 2 * lane);
        float2 v1 = *(const float2*)(hin + (size_t)s1 * 64 + 2 * lane);
        ax = fmaf(f0, v0.x, ax); ay = fmaf(f0, v0.y, ay);
        bx = fmaf(f1, v1.x, bx); by = fmaf(f1, v1.y, by);
    }
    if (j < cnt) {
        int s0 = __ldg(&g_csr[start + j]);
        float f0 = __ldg(&g_dis[s0]);
        float2 v0 = *(const float2*)(hin + (size_t)s0 * 64 + 2 * lane);
        ax = fmaf(f0, v0.x, ax); ay = fmaf(f0, v0.y, ay);
    }
    ax += bx; ay += by;

    float2 hi = *(const float2*)(hin + (size_t)i * 64 + 2 * lane);
    float2 bb = *(const float2*)(b + 2 * lane);
    float dii = di * di;
    float ox = fmaf(di, ax, fmaf(dii, hi.x, bb.x));
    float oy = fmaf(di, ay, fmaf(dii, hi.y, bb.y));
    *(float2*)(hout + (size_t)i * 64 + 2 * lane) = make_float2(fmaxf(ox, 0.f), fmaxf(oy, 0.f));
}

__global__ void k_agg32(const float* __restrict__ b) {
    int warp = (blockIdx.x * blockDim.x + threadIdx.x) >> 5;
    int lane = threadIdx.x & 31;
    if (warp >= N_NODES) return;
    const float* hin = (const float*)g_h1;
    float* hout = (float*)g_h2;

    int i = warp;
    float di = g_dis[i];
    int start = g_off[i];
    int cnt = g_deg[i];

    float a0 = 0.f, b0 = 0.f;
    int j = 0;
    for (; j + 2 <= cnt; j += 2) {
        int s0 = __ldg(&g_csr[start + j]);
        int s1 = __ldg(&g_csr[start + j + 1]);
        float f0 = __ldg(&g_dis[s0]);
        float f1 = __ldg(&g_dis[s1]);
        a0 = fmaf(f0, hin[(size_t)s0 * 32 + lane], a0);
        b0 = fmaf(f1, hin[(size_t)s1 * 32 + lane], b0);
    }
    if (j < cnt) {
        int s0 = __ldg(&g_csr[start + j]);
        float f0 = __ldg(&g_dis[s0]);
        a0 = fmaf(f0, hin[(size_t)s0 * 32 + lane], a0);
    }
    a0 += b0;

    float o0 = fmaf(di, a0, fmaf(di * di, hin[(size_t)i * 32 + lane], b[lane]));
    hout[(size_t)i * 32 + lane] = fmaxf(o0, 0.0f);
}

// ---------------- pool + classifier (batch sorted) ----------------
__device__ __forceinline__ int lowerb(const void* a, int n, long long key, int is64) {
    int lo = 0, hi = n;
    while (lo < hi) {
        int mid = (lo + hi) >> 1;
        if (load_idx(a, mid, is64) < key) lo = mid + 1; else hi = mid;
    }
    return lo;
}

__global__ void k_pool(const void* __restrict__ batch,
                       const float* __restrict__ Wc1, const float* __restrict__ bc1,
                       const float* __restrict__ Wc2, const float* __restrict__ bc2,
                       float* __restrict__ out) {
    int warp = (blockIdx.x * blockDim.x + threadIdx.x) >> 5;
    int lane = threadIdx.x & 31;
    int wl = (threadIdx.x >> 5);
    if (warp >= N_GRAPHS) return;
    const float* h3 = (const float*)g_h2;
    int is64 = g_is64;

    long long g = warp;
    int start = lowerb(batch, N_NODES, g, is64);
    int end = lowerb(batch, N_NODES, g + 1, is64);

    float acc = 0.0f;
    for (int r = start; r < end; r++) acc += h3[(size_t)r * EMB + lane];
    float cnt = (float)(end - start);
    float emb = acc / fmaxf(cnt, 1.0f);

    __shared__ float sh[8][EMB];
    sh[wl][lane] = emb;
    __syncwarp();

    float partial = 0.0f;
    if (lane < 16) {
        float t = bc1[lane];
#pragma unroll
        for (int c = 0; c < EMB; c++) t = fmaf(sh[wl][c], Wc1[c * 16 + lane], t);
        t = fmaxf(t, 0.0f);
        partial = t * Wc2[lane];
    }
#pragma unroll
    for (int o = 8; o > 0; o >>= 1) partial += __shfl_down_sync(0xffffffffu, partial, o);
    if (lane == 0) out[g] = partial + bc2[0];
}

// ---------------- launch ----------------
extern "C" void kernel_launch(void* const* d_in, const int* in_sizes, int n_in,
                              void* d_out, int out_size) {
    const float* x     = (const float*)d_in[0];
    const void*  ei    = d_in[1];
    const void*  batch = d_in[2];
    const float* W1 = (const float*)d_in[3];  const float* b1 = (const float*)d_in[4];
    const float* W2 = (const float*)d_in[5];  const float* b2 = (const float*)d_in[6];
    const float* W3 = (const float*)d_in[7];  const float* b3 = (const float*)d_in[8];
    const float* Wc1 = (const float*)d_in[9]; const float* bc1 = (const float*)d_in[10];
    const float* Wc2 = (const float*)d_in[11]; const float* bc2 = (const float*)d_in[12];
    float* out = (float*)d_out;

    const int NB_N1024 = (N_NODES + 1023) / 1024;   // 196
    const int NB_E256  = (N_EDGES + 255) / 256;     // 4883
    const int NB_N256  = (N_NODES + 255) / 256;

    const int GEMM_BLKS  = (N_NODES + 127) / 128;        // 1563
    const int COUNT_BLKS = (N_EDGES + 1023) / 1024;      // 1221
    const int AGG_BLKS   = (N_NODES * 32 + 255) / 256;   // 25000

    // zero degrees + dtype detect
    k_zero_detect<<<NB_N1024, 1024>>>((const unsigned*)ei);
    // gemm1 fused with degree count (independent work, overlapped in one grid)
    k_gemm<128, 64, true, true><<<GEMM_BLKS + COUNT_BLKS, 256>>>(x, W1, N_NODES, GEMM_BLKS, ei);
    // scans + CSR fill
    k_scan1<<<NB_N1024, 1024>>>();
    k_scan2<<<1, 256>>>(NB_N1024);
    k_scan3<<<NB_N256, 256>>>();
    k_fill_csr<<<NB_E256, 256>>>(ei);

    // layer 1 aggregation
    k_agg64<<<AGG_BLKS, 256>>>(b1);
    // layer 2: 64 -> 64
    k_gemm<64, 64, false, false><<<GEMM_BLKS, 256>>>(nullptr, W2, N_NODES, GEMM_BLKS, nullptr);
    k_agg64<<<AGG_BLKS, 256>>>(b2);
    // layer 3: 64 -> 32
    k_gemm<64, 32, false, false><<<GEMM_BLKS, 256>>>(nullptr, W3, N_NODES, GEMM_BLKS, nullptr);
    k_agg32<<<AGG_BLKS, 256>>>(b3);

    // pool + classifier
    k_pool<<<N_GRAPHS / 8, 256>>>(batch, Wc1, bc1, Wc2, bc2, out);
}